// round 13
// baseline (speedup 1.0000x reference)
#include <cuda_runtime.h>
#include <cstdint>

#define L_SEQ 2048
#define D_DIM 768
#define K_F   16
#define NFFT  4096
#define KU    3
#define C_CONV (2 * K_F * D_DIM)          // 24576
#define C_TOT  (C_CONV + KU * D_DIM)      // 26880
#define NKT    (C_TOT / 16)               // 1680

// g_Ubig: (C, L) with columns permuted within each 16-l block:
//   logical l -> physical (l & ~15) | ((l & 7) << 1) | ((l >> 3) & 1)
__device__ __align__(16) float  g_Ubig[(size_t)C_TOT * L_SEQ];
// g_Mbig: quad layout [cg = c/8][og2 = o-pair][16]:
//   og2 for o: (o>>4)*8 + (o&7), pairs (o, o+8)
//   inner[col*4 + h*2 + j] = M[c0+col+4j][o_lo + 8h] (tf32-rounded, sigma folded)
__device__ __align__(16) float  g_Mbig[(size_t)C_TOT * D_DIM];
__device__ __align__(16) float2 g_Z[D_DIM * NFFT];
__device__ __align__(16) float2 g_V[K_F * NFFT];
__device__ __align__(16) float2 g_tw[NFFT];

__device__ __forceinline__ float2 cadd(float2 a, float2 b) { return make_float2(a.x + b.x, a.y + b.y); }
__device__ __forceinline__ float2 csub(float2 a, float2 b) { return make_float2(a.x - b.x, a.y - b.y); }
__device__ __forceinline__ float2 cmul(float2 a, float2 b) {
    return make_float2(a.x * b.x - a.y * b.y, a.x * b.y + a.y * b.x);
}
__device__ __forceinline__ float2 cmulconj(float2 a, float2 w) {
    return make_float2(a.x * w.x + a.y * w.y, a.y * w.x - a.x * w.y);
}
__device__ __forceinline__ float to_tf32(float x) {
    float r; asm("cvt.rna.tf32.f32 %0, %1;" : "=f"(r) : "f"(x)); return r;
}
__device__ __forceinline__ int sphys(int i) { return i + (i >> 4) + (i >> 8); }
__device__ __forceinline__ int perm16(int i) {
    return (i & ~15) | ((i & 7) << 1) | ((i >> 3) & 1);
}
#define SMEM_FFT 4368

__global__ void k_twiddle() {
    int j = blockIdx.x * blockDim.x + threadIdx.x;
    if (j < NFFT) {
        float s, c;
        sincospif(-2.0f * (float)j / (float)NFFT, &s, &c);
        g_tw[j] = make_float2(c, s);
    }
}

// ---- radix-4 butterflies ----
__device__ __forceinline__ void bf4_dif(float2& e0, float2& e1, float2& e2, float2& e3,
                                        float2 w1, float2 w2, float2 w3) {
    float2 t0 = cadd(e0, e2), t1 = csub(e0, e2);
    float2 t2 = cadd(e1, e3), t3 = csub(e1, e3);
    float2 t3m = make_float2(t3.y, -t3.x);
    e0 = cadd(t0, t2); e1 = cmul(cadd(t1, t3m), w1);
    e2 = cmul(csub(t0, t2), w2); e3 = cmul(csub(t1, t3m), w3);
}
__device__ __forceinline__ void bf4_dif_nw(float2& e0, float2& e1, float2& e2, float2& e3) {
    float2 t0 = cadd(e0, e2), t1 = csub(e0, e2);
    float2 t2 = cadd(e1, e3), t3 = csub(e1, e3);
    float2 t3m = make_float2(t3.y, -t3.x);
    e0 = cadd(t0, t2); e1 = cadd(t1, t3m); e2 = csub(t0, t2); e3 = csub(t1, t3m);
}
__device__ __forceinline__ void bf4_dit(float2& e0, float2& e1, float2& e2, float2& e3,
                                        float2 w1, float2 w2, float2 w3) {
    float2 u1 = cmulconj(e1, w1), u2 = cmulconj(e2, w2), u3 = cmulconj(e3, w3);
    float2 t0 = cadd(e0, u2), t1 = csub(e0, u2);
    float2 t2 = cadd(u1, u3), t3 = csub(u1, u3);
    float2 it3 = make_float2(-t3.y, t3.x);
    e0 = cadd(t0, t2); e1 = cadd(t1, it3); e2 = csub(t0, t2); e3 = csub(t1, it3);
}
__device__ __forceinline__ void bf4_dit_nw(float2& e0, float2& e1, float2& e2, float2& e3) {
    float2 t0 = cadd(e0, e2), t1 = csub(e0, e2);
    float2 t2 = cadd(e1, e3), t3 = csub(e1, e3);
    float2 it3 = make_float2(-t3.y, t3.x);
    e0 = cadd(t0, t2); e1 = cadd(t1, it3); e2 = csub(t0, t2); e3 = csub(t1, it3);
}

template <int Q2, int STEP, int HT>
__device__ __forceinline__ void fwd_pass(float2* r, int j) {
    #pragma unroll
    for (int b = 0; b < 4; b++) {
        float2 w1 = g_tw[(j + b * Q2) * STEP];
        float2 w2 = cmul(w1, w1), w3 = cmul(w2, w1);
        bf4_dif(r[b], r[4 + b], r[8 + b], r[12 + b], w1, w2, w3);
    }
    if (HT) {
        #pragma unroll
        for (int a = 0; a < 4; a++) bf4_dif_nw(r[4 * a], r[4 * a + 1], r[4 * a + 2], r[4 * a + 3]);
    } else {
        float2 w1 = g_tw[j * STEP * 4];
        float2 w2 = cmul(w1, w1), w3 = cmul(w2, w1);
        #pragma unroll
        for (int a = 0; a < 4; a++) bf4_dif(r[4 * a], r[4 * a + 1], r[4 * a + 2], r[4 * a + 3], w1, w2, w3);
    }
}
template <int Q2, int STEP, int HT>
__device__ __forceinline__ void inv_pass(float2* r, int j) {
    if (HT) {
        #pragma unroll
        for (int a = 0; a < 4; a++) bf4_dit_nw(r[4 * a], r[4 * a + 1], r[4 * a + 2], r[4 * a + 3]);
    } else {
        float2 w1 = g_tw[j * STEP * 4];
        float2 w2 = cmul(w1, w1), w3 = cmul(w2, w1);
        #pragma unroll
        for (int a = 0; a < 4; a++) bf4_dit(r[4 * a], r[4 * a + 1], r[4 * a + 2], r[4 * a + 3], w1, w2, w3);
    }
    #pragma unroll
    for (int b = 0; b < 4; b++) {
        float2 w1 = g_tw[(j + b * Q2) * STEP];
        float2 w2 = cmul(w1, w1), w3 = cmul(w2, w1);
        bf4_dit(r[b], r[4 + b], r[8 + b], r[12 + b], w1, w2, w3);
    }
}

// ---- forward FFT: 768 packed x-channels + 16 phi-channels ----
__global__ void __launch_bounds__(256) k_fft_fwd(const float* __restrict__ x,
                                                 const float* __restrict__ phi) {
    __shared__ float2 S[SMEM_FFT];
    const int blk = blockIdx.x, tid = threadIdx.x;
    float2 r[16];
    #pragma unroll
    for (int a = 0; a < 4; a++)
        #pragma unroll
        for (int b = 0; b < 4; b++) {
            int idx = tid + a * 1024 + b * 256;
            if (blk < D_DIM) {
                float v = (idx < L_SEQ) ? __ldg(x + (size_t)idx * D_DIM + blk) : 0.0f;
                r[a * 4 + b] = make_float2(v, (idx & 1) ? -v : v);
            } else {
                float v = (idx < L_SEQ) ? __ldg(phi + (size_t)idx * K_F + (blk - D_DIM)) : 0.0f;
                r[a * 4 + b] = make_float2(v, 0.0f);
            }
        }
    fwd_pass<256, 1, 0>(r, tid);
    #pragma unroll
    for (int a = 0; a < 4; a++)
        #pragma unroll
        for (int b = 0; b < 4; b++) S[sphys(tid + a * 1024 + b * 256)] = r[a * 4 + b];
    __syncthreads();
    {
        const int g = tid >> 4, j = tid & 15, base = g * 256 + j;
        #pragma unroll
        for (int a = 0; a < 4; a++)
            #pragma unroll
            for (int b = 0; b < 4; b++) r[a * 4 + b] = S[sphys(base + a * 64 + b * 16)];
        fwd_pass<16, 16, 0>(r, j);
        #pragma unroll
        for (int a = 0; a < 4; a++)
            #pragma unroll
            for (int b = 0; b < 4; b++) S[sphys(base + a * 64 + b * 16)] = r[a * 4 + b];
    }
    __syncthreads();
    {
        const int base = tid * 16;
        #pragma unroll
        for (int a = 0; a < 4; a++)
            #pragma unroll
            for (int b = 0; b < 4; b++) r[a * 4 + b] = S[sphys(base + a * 4 + b)];
        fwd_pass<1, 256, 1>(r, 0);
        float2* out = (blk < D_DIM) ? (g_Z + (size_t)blk * NFFT) : (g_V + (size_t)(blk - D_DIM) * NFFT);
        #pragma unroll
        for (int i = 0; i < 16; i++) out[base + i] = r[i];
    }
}

// ---- per-(k,d): fused pointwise V*Z + inverse FFT, write tf32 (permuted columns) ----
__global__ void __launch_bounds__(256) k_conv_inv() {
    __shared__ float2 S[SMEM_FFT];
    const int blk = blockIdx.x;
    const int k = blk / D_DIM, d = blk - k * D_DIM;
    const int tid = threadIdx.x;
    const float2* Z = g_Z + (size_t)d * NFFT;
    const float2* V = g_V + (size_t)k * NFFT;
    float2 r[16];
    {   // pass A fused with pointwise product
        const int base = tid * 16;
        #pragma unroll
        for (int i = 0; i < 16; i++) r[i] = cmul(Z[base + i], V[base + i]);
        inv_pass<1, 256, 1>(r, 0);
        #pragma unroll
        for (int a = 0; a < 4; a++)
            #pragma unroll
            for (int b = 0; b < 4; b++) S[sphys(base + a * 4 + b)] = r[a * 4 + b];
    }
    __syncthreads();
    {   // pass B
        const int g = tid >> 4, j = tid & 15, base = g * 256 + j;
        #pragma unroll
        for (int a = 0; a < 4; a++)
            #pragma unroll
            for (int b = 0; b < 4; b++) r[a * 4 + b] = S[sphys(base + a * 64 + b * 16)];
        inv_pass<16, 16, 0>(r, j);
        #pragma unroll
        for (int a = 0; a < 4; a++)
            #pragma unroll
            for (int b = 0; b < 4; b++) S[sphys(base + a * 64 + b * 16)] = r[a * 4 + b];
    }
    __syncthreads();
    {   // pass C: natural order out, keep idx < 2048, write gmem (perm16 columns)
        #pragma unroll
        for (int a = 0; a < 4; a++)
            #pragma unroll
            for (int b = 0; b < 4; b++) r[a * 4 + b] = S[sphys(tid + a * 1024 + b * 256)];
        inv_pass<256, 1, 0>(r, tid);
        const float inv = 1.0f / (float)NFFT;
        float* up = g_Ubig + (size_t)(k * D_DIM + d) * L_SEQ;
        float* um = g_Ubig + (size_t)(C_CONV / 2 + k * D_DIM + d) * L_SEQ;
        #pragma unroll
        for (int a = 0; a < 2; a++)
            #pragma unroll
            for (int b = 0; b < 4; b++) {
                int idx = tid + a * 1024 + b * 256;
                int p = perm16(idx);
                float2 v = r[a * 4 + b];
                up[p] = to_tf32(v.x * inv);
                um[p] = to_tf32(((idx & 1) ? -v.y : v.y) * inv);
            }
    }
}

// ---- AR channels via coalesced 32x32 transpose tiles (perm16 columns) ----
__global__ void k_arfill(const float* __restrict__ x) {
    __shared__ float T[32][33];
    const int tx = threadIdx.x, ty = threadIdx.y;
    const int lb = blockIdx.x * 32, cb = blockIdx.y * 32;
    const int i = cb / D_DIM, d0 = cb - i * D_DIM;
    #pragma unroll
    for (int rr = 0; rr < 4; rr++) {
        int l = lb + ty + rr * 8;
        T[ty + rr * 8][tx] = (l >= i) ? x[(size_t)(l - i) * D_DIM + d0 + tx] : 0.0f;
    }
    __syncthreads();
    #pragma unroll
    for (int rr = 0; rr < 4; rr++) {
        int cl = ty + rr * 8;
        g_Ubig[(size_t)(C_CONV + cb + cl) * L_SEQ + lb + perm16(tx)] = to_tf32(T[tx][cl]);
    }
}

// ---- pack [Mp*sig4 ; Mm*sig4 ; Mu] into quad layout [cg][og2][16] ----
__global__ void __launch_bounds__(256) k_mbig(const float* __restrict__ Mp,
                                              const float* __restrict__ Mm,
                                              const float* __restrict__ Mu,
                                              const float* __restrict__ sigma) {
    const int cg = blockIdx.x;           // 0 .. C_TOT/8-1
    const int c0 = cg * 8;
    const float* src; float scale; int row0;
    if (c0 < K_F * D_DIM) {
        src = Mp; row0 = c0; scale = powf(sigma[c0 / D_DIM], 0.25f);
    } else if (c0 < 2 * K_F * D_DIM) {
        src = Mm; row0 = c0 - K_F * D_DIM; scale = powf(sigma[row0 / D_DIM], 0.25f);
    } else {
        src = Mu; row0 = c0 - 2 * K_F * D_DIM; scale = 1.0f;
    }
    for (int og2 = threadIdx.x; og2 < D_DIM / 2; og2 += 256) {
        const int o_lo = ((og2 >> 3) << 4) | (og2 & 7);
        float buf[16];
        #pragma unroll
        for (int col = 0; col < 4; col++)
            #pragma unroll
            for (int h = 0; h < 2; h++)
                #pragma unroll
                for (int j = 0; j < 2; j++)
                    buf[col * 4 + h * 2 + j] =
                        to_tf32(src[(size_t)(row0 + col + 4 * j) * D_DIM + o_lo + 8 * h] * scale);
        float4* dst = (float4*)(g_Mbig + ((size_t)cg * (D_DIM / 2) + og2) * 16);
        #pragma unroll
        for (int p = 0; p < 4; p++) dst[p] = ((const float4*)buf)[p];
    }
}

// ---- TF32 GEMM: 128x96 tile, full-K, 3-stage cp.async, LDS.64 A / LDS.128 B ----
__device__ __forceinline__ void mma_tf32(float* acc, const uint32_t* a, const uint32_t* b) {
    asm volatile(
        "mma.sync.aligned.m16n8k8.row.col.f32.tf32.tf32.f32 "
        "{%0,%1,%2,%3}, {%4,%5,%6,%7}, {%8,%9}, {%0,%1,%2,%3};"
        : "+f"(acc[0]), "+f"(acc[1]), "+f"(acc[2]), "+f"(acc[3])
        : "r"(a[0]), "r"(a[1]), "r"(a[2]), "r"(a[3]), "r"(b[0]), "r"(b[1]));
}
__device__ __forceinline__ void cp16(uint32_t dst, const float* src) {
    asm volatile("cp.async.cg.shared.global [%0], [%1], 16;" :: "r"(dst), "l"(src));
}

__global__ void __launch_bounds__(256) k_gemm(float* __restrict__ out) {
    __shared__ float As[3][16][136];      // [k16][m128 physical-permuted]
    __shared__ float Bs[3][2][48][16];    // [k8-group][og2][quad of 16]
    const int tid = threadIdx.x, lane = tid & 31, warp = tid >> 5;
    const int mbase = blockIdx.y * 128, nbase = blockIdx.x * 96;
    const int wm = (warp & 3) * 32, wn = (warp >> 2) * 48;
    const int row = lane >> 2, col = lane & 3;
    const int wcol8 = (wn >> 4) * 8;      // og2 base offset for this warp

    float acc[2][6][4];
    #pragma unroll
    for (int mi = 0; mi < 2; mi++)
        #pragma unroll
        for (int ni = 0; ni < 6; ni++)
            #pragma unroll
            for (int q = 0; q < 4; q++) acc[mi][ni][q] = 0.0f;

    auto PREFETCH = [&](int kt, int st) {
        size_t kb = (size_t)kt * 16;
        // A: 16 rows x 128 floats = 512 float4; 2 per thread
        #pragma unroll
        for (int i = 0; i < 2; i++) {
            int idx = tid + i * 256;
            int rA = idx >> 5, c4 = (idx & 31) * 4;
            cp16((uint32_t)__cvta_generic_to_shared(&As[st][rA][c4]),
                 g_Ubig + (kb + rA) * L_SEQ + mbase + c4);
        }
        // B: 2 cgs x 48 og2 x 16 floats = 384 float4; threads 0..191 do 2 (contiguous tile)
        if (tid < 192) {
            size_t cg0 = kb >> 3;         // = kt*2
            #pragma unroll
            for (int cg = 0; cg < 2; cg++) {
                cp16((uint32_t)__cvta_generic_to_shared(&Bs[st][cg][tid >> 2][(tid & 3) * 4]),
                     g_Mbig + (cg0 + cg) * (size_t)(D_DIM / 2) * 16 + (size_t)nbase * 8 + tid * 4);
            }
        }
        asm volatile("cp.async.commit_group;");
    };

    PREFETCH(0, 0);
    PREFETCH(1, 1);

    int st = 0;
    for (int kt = 0; kt < NKT; kt++) {
        if (kt + 1 < NKT) asm volatile("cp.async.wait_group 1;");
        else              asm volatile("cp.async.wait_group 0;");
        __syncthreads();
        if (kt + 2 < NKT) {
            int st2 = st + 2; if (st2 >= 3) st2 -= 3;
            PREFETCH(kt + 2, st2);
        }
        #pragma unroll
        for (int ks = 0; ks < 2; ks++) {
            const int k8 = ks * 8;
            uint32_t a[2][4], b[6][2];
            #pragma unroll
            for (int mi = 0; mi < 2; mi++) {
                const int pc = wm + mi * 16 + 2 * row;
                float2 p0 = *(const float2*)&As[st][k8 + col][pc];
                float2 p1 = *(const float2*)&As[st][k8 + col + 4][pc];
                a[mi][0] = __float_as_uint(p0.x);
                a[mi][1] = __float_as_uint(p0.y);
                a[mi][2] = __float_as_uint(p1.x);
                a[mi][3] = __float_as_uint(p1.y);
            }
            #pragma unroll
            for (int pi = 0; pi < 3; pi++) {
                float4 pb = *(const float4*)&Bs[st][ks][wcol8 + pi * 8 + row][col * 4];
                b[2 * pi][0]     = __float_as_uint(pb.x);
                b[2 * pi][1]     = __float_as_uint(pb.y);
                b[2 * pi + 1][0] = __float_as_uint(pb.z);
                b[2 * pi + 1][1] = __float_as_uint(pb.w);
            }
            #pragma unroll
            for (int mi = 0; mi < 2; mi++)
                #pragma unroll
                for (int ni = 0; ni < 6; ni++)
                    mma_tf32(acc[mi][ni], a[mi], b[ni]);
        }
        if (++st >= 3) st = 0;
    }

    #pragma unroll
    for (int mi = 0; mi < 2; mi++)
        #pragma unroll
        for (int ni = 0; ni < 6; ni++) {
            int r0 = mbase + wm + mi * 16 + row;
            int c0 = nbase + wn + ni * 8 + col * 2;
            out[(size_t)r0 * D_DIM + c0]           = acc[mi][ni][0];
            out[(size_t)r0 * D_DIM + c0 + 1]       = acc[mi][ni][1];
            out[(size_t)(r0 + 8) * D_DIM + c0]     = acc[mi][ni][2];
            out[(size_t)(r0 + 8) * D_DIM + c0 + 1] = acc[mi][ni][3];
        }
}

extern "C" void kernel_launch(void* const* d_in, const int* in_sizes, int n_in,
                              void* d_out, int out_size) {
    const float* x     = (const float*)d_in[0];
    const float* phi   = (const float*)d_in[1];
    const float* sigma = (const float*)d_in[2];
    const float* Mp    = (const float*)d_in[3];
    const float* Mm    = (const float*)d_in[4];
    const float* Mu    = (const float*)d_in[5];
    (void)in_sizes; (void)n_in; (void)out_size;

    k_twiddle<<<NFFT / 256, 256>>>();
    k_fft_fwd<<<D_DIM + K_F, 256>>>(x, phi);
    k_conv_inv<<<K_F * D_DIM, 256>>>();
    k_arfill<<<dim3(L_SEQ / 32, KU * D_DIM / 32), dim3(32, 8)>>>(x);
    k_mbig<<<C_TOT / 8, 256>>>(Mp, Mm, Mu, sigma);
    k_gemm<<<dim3(D_DIM / 96, L_SEQ / 128), 256>>>((float*)d_out);
}

// round 14
// speedup vs baseline: 1.1916x; 1.1916x over previous
#include <cuda_runtime.h>
#include <cstdint>

#define L_SEQ 2048
#define D_DIM 768
#define K_F   16
#define NFFT  4096
#define KU    3
#define C_CONV (2 * K_F * D_DIM)          // 24576
#define C_TOT  (C_CONV + KU * D_DIM)      // 26880
#define KSPL   (C_TOT / 2)                // 13440
#define NKT_S  (KSPL / 16)                // 840

// g_Ubig: (C, L) with columns permuted within each 16-l block:
//   logical l -> physical (l & ~15) | ((l & 7) << 1) | ((l >> 3) & 1)
__device__ __align__(16) float  g_Ubig[(size_t)C_TOT * L_SEQ];
// g_Mbig: quad layout [cg = c/8][og2 = o-pair][16]:
//   og2 for o: (o>>4)*8 + (o&7), pairs (o, o+8)
//   inner[col*4 + h*2 + j] = M[c0+col+4j][o_lo + 8h] (tf32-rounded, sigma folded)
__device__ __align__(16) float  g_Mbig[(size_t)C_TOT * D_DIM];
__device__ __align__(16) float  g_part[2][(size_t)L_SEQ * D_DIM];
__device__ __align__(16) float2 g_Z[D_DIM * NFFT];
__device__ __align__(16) float2 g_V[K_F * NFFT];
__device__ __align__(16) float2 g_tw[NFFT];

__device__ __forceinline__ float2 cadd(float2 a, float2 b) { return make_float2(a.x + b.x, a.y + b.y); }
__device__ __forceinline__ float2 csub(float2 a, float2 b) { return make_float2(a.x - b.x, a.y - b.y); }
__device__ __forceinline__ float2 cmul(float2 a, float2 b) {
    return make_float2(a.x * b.x - a.y * b.y, a.x * b.y + a.y * b.x);
}
__device__ __forceinline__ float2 cmulconj(float2 a, float2 w) {
    return make_float2(a.x * w.x + a.y * w.y, a.y * w.x - a.x * w.y);
}
__device__ __forceinline__ float to_tf32(float x) {
    float r; asm("cvt.rna.tf32.f32 %0, %1;" : "=f"(r) : "f"(x)); return r;
}
__device__ __forceinline__ int sphys(int i) { return i + (i >> 4) + (i >> 8); }
__device__ __forceinline__ int perm16(int i) {
    return (i & ~15) | ((i & 7) << 1) | ((i >> 3) & 1);
}
#define SMEM_FFT 4368

__global__ void k_twiddle() {
    int j = blockIdx.x * blockDim.x + threadIdx.x;
    if (j < NFFT) {
        float s, c;
        sincospif(-2.0f * (float)j / (float)NFFT, &s, &c);
        g_tw[j] = make_float2(c, s);
    }
}

// ---- radix-4 butterflies ----
__device__ __forceinline__ void bf4_dif(float2& e0, float2& e1, float2& e2, float2& e3,
                                        float2 w1, float2 w2, float2 w3) {
    float2 t0 = cadd(e0, e2), t1 = csub(e0, e2);
    float2 t2 = cadd(e1, e3), t3 = csub(e1, e3);
    float2 t3m = make_float2(t3.y, -t3.x);
    e0 = cadd(t0, t2); e1 = cmul(cadd(t1, t3m), w1);
    e2 = cmul(csub(t0, t2), w2); e3 = cmul(csub(t1, t3m), w3);
}
__device__ __forceinline__ void bf4_dif_nw(float2& e0, float2& e1, float2& e2, float2& e3) {
    float2 t0 = cadd(e0, e2), t1 = csub(e0, e2);
    float2 t2 = cadd(e1, e3), t3 = csub(e1, e3);
    float2 t3m = make_float2(t3.y, -t3.x);
    e0 = cadd(t0, t2); e1 = cadd(t1, t3m); e2 = csub(t0, t2); e3 = csub(t1, t3m);
}
__device__ __forceinline__ void bf4_dit(float2& e0, float2& e1, float2& e2, float2& e3,
                                        float2 w1, float2 w2, float2 w3) {
    float2 u1 = cmulconj(e1, w1), u2 = cmulconj(e2, w2), u3 = cmulconj(e3, w3);
    float2 t0 = cadd(e0, u2), t1 = csub(e0, u2);
    float2 t2 = cadd(u1, u3), t3 = csub(u1, u3);
    float2 it3 = make_float2(-t3.y, t3.x);
    e0 = cadd(t0, t2); e1 = cadd(t1, it3); e2 = csub(t0, t2); e3 = csub(t1, it3);
}
__device__ __forceinline__ void bf4_dit_nw(float2& e0, float2& e1, float2& e2, float2& e3) {
    float2 t0 = cadd(e0, e2), t1 = csub(e0, e2);
    float2 t2 = cadd(e1, e3), t3 = csub(e1, e3);
    float2 it3 = make_float2(-t3.y, t3.x);
    e0 = cadd(t0, t2); e1 = cadd(t1, it3); e2 = csub(t0, t2); e3 = csub(t1, it3);
}

template <int Q2, int STEP, int HT>
__device__ __forceinline__ void fwd_pass(float2* r, int j) {
    #pragma unroll
    for (int b = 0; b < 4; b++) {
        float2 w1 = g_tw[(j + b * Q2) * STEP];
        float2 w2 = cmul(w1, w1), w3 = cmul(w2, w1);
        bf4_dif(r[b], r[4 + b], r[8 + b], r[12 + b], w1, w2, w3);
    }
    if (HT) {
        #pragma unroll
        for (int a = 0; a < 4; a++) bf4_dif_nw(r[4 * a], r[4 * a + 1], r[4 * a + 2], r[4 * a + 3]);
    } else {
        float2 w1 = g_tw[j * STEP * 4];
        float2 w2 = cmul(w1, w1), w3 = cmul(w2, w1);
        #pragma unroll
        for (int a = 0; a < 4; a++) bf4_dif(r[4 * a], r[4 * a + 1], r[4 * a + 2], r[4 * a + 3], w1, w2, w3);
    }
}
template <int Q2, int STEP, int HT>
__device__ __forceinline__ void inv_pass(float2* r, int j) {
    if (HT) {
        #pragma unroll
        for (int a = 0; a < 4; a++) bf4_dit_nw(r[4 * a], r[4 * a + 1], r[4 * a + 2], r[4 * a + 3]);
    } else {
        float2 w1 = g_tw[j * STEP * 4];
        float2 w2 = cmul(w1, w1), w3 = cmul(w2, w1);
        #pragma unroll
        for (int a = 0; a < 4; a++) bf4_dit(r[4 * a], r[4 * a + 1], r[4 * a + 2], r[4 * a + 3], w1, w2, w3);
    }
    #pragma unroll
    for (int b = 0; b < 4; b++) {
        float2 w1 = g_tw[(j + b * Q2) * STEP];
        float2 w2 = cmul(w1, w1), w3 = cmul(w2, w1);
        bf4_dit(r[b], r[4 + b], r[8 + b], r[12 + b], w1, w2, w3);
    }
}

// ---- forward FFT: 768 packed x-channels + 16 phi-channels ----
__global__ void __launch_bounds__(256) k_fft_fwd(const float* __restrict__ x,
                                                 const float* __restrict__ phi) {
    __shared__ float2 S[SMEM_FFT];
    const int blk = blockIdx.x, tid = threadIdx.x;
    float2 r[16];
    #pragma unroll
    for (int a = 0; a < 4; a++)
        #pragma unroll
        for (int b = 0; b < 4; b++) {
            int idx = tid + a * 1024 + b * 256;
            if (blk < D_DIM) {
                float v = (idx < L_SEQ) ? __ldg(x + (size_t)idx * D_DIM + blk) : 0.0f;
                r[a * 4 + b] = make_float2(v, (idx & 1) ? -v : v);
            } else {
                float v = (idx < L_SEQ) ? __ldg(phi + (size_t)idx * K_F + (blk - D_DIM)) : 0.0f;
                r[a * 4 + b] = make_float2(v, 0.0f);
            }
        }
    fwd_pass<256, 1, 0>(r, tid);
    #pragma unroll
    for (int a = 0; a < 4; a++)
        #pragma unroll
        for (int b = 0; b < 4; b++) S[sphys(tid + a * 1024 + b * 256)] = r[a * 4 + b];
    __syncthreads();
    {
        const int g = tid >> 4, j = tid & 15, base = g * 256 + j;
        #pragma unroll
        for (int a = 0; a < 4; a++)
            #pragma unroll
            for (int b = 0; b < 4; b++) r[a * 4 + b] = S[sphys(base + a * 64 + b * 16)];
        fwd_pass<16, 16, 0>(r, j);
        #pragma unroll
        for (int a = 0; a < 4; a++)
            #pragma unroll
            for (int b = 0; b < 4; b++) S[sphys(base + a * 64 + b * 16)] = r[a * 4 + b];
    }
    __syncthreads();
    {
        const int base = tid * 16;
        #pragma unroll
        for (int a = 0; a < 4; a++)
            #pragma unroll
            for (int b = 0; b < 4; b++) r[a * 4 + b] = S[sphys(base + a * 4 + b)];
        fwd_pass<1, 256, 1>(r, 0);
        float2* out = (blk < D_DIM) ? (g_Z + (size_t)blk * NFFT) : (g_V + (size_t)(blk - D_DIM) * NFFT);
        #pragma unroll
        for (int i = 0; i < 16; i++) out[base + i] = r[i];
    }
}

// ---- per-(k,d): fused pointwise V*Z + inverse FFT, write tf32 (permuted columns) ----
__global__ void __launch_bounds__(256) k_conv_inv() {
    __shared__ float2 S[SMEM_FFT];
    const int blk = blockIdx.x;
    const int k = blk / D_DIM, d = blk - k * D_DIM;
    const int tid = threadIdx.x;
    const float2* Z = g_Z + (size_t)d * NFFT;
    const float2* V = g_V + (size_t)k * NFFT;
    float2 r[16];
    {   // pass A fused with pointwise product
        const int base = tid * 16;
        #pragma unroll
        for (int i = 0; i < 16; i++) r[i] = cmul(Z[base + i], V[base + i]);
        inv_pass<1, 256, 1>(r, 0);
        #pragma unroll
        for (int a = 0; a < 4; a++)
            #pragma unroll
            for (int b = 0; b < 4; b++) S[sphys(base + a * 4 + b)] = r[a * 4 + b];
    }
    __syncthreads();
    {   // pass B
        const int g = tid >> 4, j = tid & 15, base = g * 256 + j;
        #pragma unroll
        for (int a = 0; a < 4; a++)
            #pragma unroll
            for (int b = 0; b < 4; b++) r[a * 4 + b] = S[sphys(base + a * 64 + b * 16)];
        inv_pass<16, 16, 0>(r, j);
        #pragma unroll
        for (int a = 0; a < 4; a++)
            #pragma unroll
            for (int b = 0; b < 4; b++) S[sphys(base + a * 64 + b * 16)] = r[a * 4 + b];
    }
    __syncthreads();
    {   // pass C: natural order out, keep idx < 2048, write gmem (perm16 columns)
        #pragma unroll
        for (int a = 0; a < 4; a++)
            #pragma unroll
            for (int b = 0; b < 4; b++) r[a * 4 + b] = S[sphys(tid + a * 1024 + b * 256)];
        inv_pass<256, 1, 0>(r, tid);
        const float inv = 1.0f / (float)NFFT;
        float* up = g_Ubig + (size_t)(k * D_DIM + d) * L_SEQ;
        float* um = g_Ubig + (size_t)(C_CONV / 2 + k * D_DIM + d) * L_SEQ;
        #pragma unroll
        for (int a = 0; a < 2; a++)
            #pragma unroll
            for (int b = 0; b < 4; b++) {
                int idx = tid + a * 1024 + b * 256;
                int p = perm16(idx);
                float2 v = r[a * 4 + b];
                up[p] = to_tf32(v.x * inv);
                um[p] = to_tf32(((idx & 1) ? -v.y : v.y) * inv);
            }
    }
}

// ---- AR channels via coalesced 32x32 transpose tiles (perm16 columns) ----
__global__ void k_arfill(const float* __restrict__ x) {
    __shared__ float T[32][33];
    const int tx = threadIdx.x, ty = threadIdx.y;
    const int lb = blockIdx.x * 32, cb = blockIdx.y * 32;
    const int i = cb / D_DIM, d0 = cb - i * D_DIM;
    #pragma unroll
    for (int rr = 0; rr < 4; rr++) {
        int l = lb + ty + rr * 8;
        T[ty + rr * 8][tx] = (l >= i) ? x[(size_t)(l - i) * D_DIM + d0 + tx] : 0.0f;
    }
    __syncthreads();
    #pragma unroll
    for (int rr = 0; rr < 4; rr++) {
        int cl = ty + rr * 8;
        g_Ubig[(size_t)(C_CONV + cb + cl) * L_SEQ + lb + perm16(tx)] = to_tf32(T[tx][cl]);
    }
}

// ---- pack [Mp*sig4 ; Mm*sig4 ; Mu] into quad layout [cg][og2][16] ----
__global__ void __launch_bounds__(256) k_mbig(const float* __restrict__ Mp,
                                              const float* __restrict__ Mm,
                                              const float* __restrict__ Mu,
                                              const float* __restrict__ sigma) {
    const int cg = blockIdx.x;           // 0 .. C_TOT/8-1
    const int c0 = cg * 8;
    const float* src; float scale; int row0;
    if (c0 < K_F * D_DIM) {
        src = Mp; row0 = c0; scale = powf(sigma[c0 / D_DIM], 0.25f);
    } else if (c0 < 2 * K_F * D_DIM) {
        src = Mm; row0 = c0 - K_F * D_DIM; scale = powf(sigma[row0 / D_DIM], 0.25f);
    } else {
        src = Mu; row0 = c0 - 2 * K_F * D_DIM; scale = 1.0f;
    }
    for (int og2 = threadIdx.x; og2 < D_DIM / 2; og2 += 256) {
        const int o_lo = ((og2 >> 3) << 4) | (og2 & 7);
        float buf[16];
        #pragma unroll
        for (int col = 0; col < 4; col++)
            #pragma unroll
            for (int h = 0; h < 2; h++)
                #pragma unroll
                for (int j = 0; j < 2; j++)
                    buf[col * 4 + h * 2 + j] =
                        to_tf32(src[(size_t)(row0 + col + 4 * j) * D_DIM + o_lo + 8 * h] * scale);
        float4* dst = (float4*)(g_Mbig + ((size_t)cg * (D_DIM / 2) + og2) * 16);
        #pragma unroll
        for (int p = 0; p < 4; p++) dst[p] = ((const float4*)buf)[p];
    }
}

// ---- TF32 GEMM: 128x96 tile, split-K=2, 3-stage cp.async, LDS.64 A / LDS.128 B ----
__device__ __forceinline__ void mma_tf32(float* acc, const uint32_t* a, const uint32_t* b) {
    asm volatile(
        "mma.sync.aligned.m16n8k8.row.col.f32.tf32.tf32.f32 "
        "{%0,%1,%2,%3}, {%4,%5,%6,%7}, {%8,%9}, {%0,%1,%2,%3};"
        : "+f"(acc[0]), "+f"(acc[1]), "+f"(acc[2]), "+f"(acc[3])
        : "r"(a[0]), "r"(a[1]), "r"(a[2]), "r"(a[3]), "r"(b[0]), "r"(b[1]));
}
__device__ __forceinline__ void cp16(uint32_t dst, const float* src) {
    asm volatile("cp.async.cg.shared.global [%0], [%1], 16;" :: "r"(dst), "l"(src));
}

__global__ void __launch_bounds__(256) k_gemm() {
    __shared__ float As[3][16][136];      // [k16][m128 physical-permuted]
    __shared__ float Bs[3][2][48][16];    // [k8-group][og2][quad of 16]
    const int tid = threadIdx.x, lane = tid & 31, warp = tid >> 5;
    const int mbase = blockIdx.y * 128, nbase = blockIdx.x * 96;
    const int zoff = blockIdx.z * KSPL;
    const int wm = (warp & 3) * 32, wn = (warp >> 2) * 48;
    const int row = lane >> 2, col = lane & 3;
    const int wcol8 = (wn >> 4) * 8;      // og2 base offset for this warp

    float acc[2][6][4];
    #pragma unroll
    for (int mi = 0; mi < 2; mi++)
        #pragma unroll
        for (int ni = 0; ni < 6; ni++)
            #pragma unroll
            for (int q = 0; q < 4; q++) acc[mi][ni][q] = 0.0f;

    auto PREFETCH = [&](int kt, int st) {
        size_t kb = (size_t)(zoff + kt * 16);
        // A: 16 rows x 128 floats = 512 float4; 2 per thread
        #pragma unroll
        for (int i = 0; i < 2; i++) {
            int idx = tid + i * 256;
            int rA = idx >> 5, c4 = (idx & 31) * 4;
            cp16((uint32_t)__cvta_generic_to_shared(&As[st][rA][c4]),
                 g_Ubig + (kb + rA) * L_SEQ + mbase + c4);
        }
        // B: 2 cgs x 48 og2 x 16 floats = 384 float4; threads 0..191 do 2 (contiguous tile)
        if (tid < 192) {
            size_t cg0 = kb >> 3;
            #pragma unroll
            for (int cg = 0; cg < 2; cg++) {
                cp16((uint32_t)__cvta_generic_to_shared(&Bs[st][cg][tid >> 2][(tid & 3) * 4]),
                     g_Mbig + (cg0 + cg) * (size_t)(D_DIM / 2) * 16 + (size_t)nbase * 8 + tid * 4);
            }
        }
        asm volatile("cp.async.commit_group;");
    };

    PREFETCH(0, 0);
    PREFETCH(1, 1);

    int st = 0;
    for (int kt = 0; kt < NKT_S; kt++) {
        if (kt + 1 < NKT_S) asm volatile("cp.async.wait_group 1;");
        else                asm volatile("cp.async.wait_group 0;");
        __syncthreads();
        if (kt + 2 < NKT_S) {
            int st2 = st + 2; if (st2 >= 3) st2 -= 3;
            PREFETCH(kt + 2, st2);
        }
        #pragma unroll
        for (int ks = 0; ks < 2; ks++) {
            const int k8 = ks * 8;
            uint32_t a[2][4], b[6][2];
            #pragma unroll
            for (int mi = 0; mi < 2; mi++) {
                const int pc = wm + mi * 16 + 2 * row;
                float2 p0 = *(const float2*)&As[st][k8 + col][pc];
                float2 p1 = *(const float2*)&As[st][k8 + col + 4][pc];
                a[mi][0] = __float_as_uint(p0.x);
                a[mi][1] = __float_as_uint(p0.y);
                a[mi][2] = __float_as_uint(p1.x);
                a[mi][3] = __float_as_uint(p1.y);
            }
            #pragma unroll
            for (int pi = 0; pi < 3; pi++) {
                float4 pb = *(const float4*)&Bs[st][ks][wcol8 + pi * 8 + row][col * 4];
                b[2 * pi][0]     = __float_as_uint(pb.x);
                b[2 * pi][1]     = __float_as_uint(pb.y);
                b[2 * pi + 1][0] = __float_as_uint(pb.z);
                b[2 * pi + 1][1] = __float_as_uint(pb.w);
            }
            #pragma unroll
            for (int mi = 0; mi < 2; mi++)
                #pragma unroll
                for (int ni = 0; ni < 6; ni++)
                    mma_tf32(acc[mi][ni], a[mi], b[ni]);
        }
        if (++st >= 3) st = 0;
    }

    float* dst = g_part[blockIdx.z];
    #pragma unroll
    for (int mi = 0; mi < 2; mi++)
        #pragma unroll
        for (int ni = 0; ni < 6; ni++) {
            int r0 = mbase + wm + mi * 16 + row;
            int c0 = nbase + wn + ni * 8 + col * 2;
            dst[(size_t)r0 * D_DIM + c0]           = acc[mi][ni][0];
            dst[(size_t)r0 * D_DIM + c0 + 1]       = acc[mi][ni][1];
            dst[(size_t)(r0 + 8) * D_DIM + c0]     = acc[mi][ni][2];
            dst[(size_t)(r0 + 8) * D_DIM + c0 + 1] = acc[mi][ni][3];
        }
}

// ---- deterministic split-K reduce ----
__global__ void __launch_bounds__(256) k_reduce(float* __restrict__ out) {
    int i = blockIdx.x * 256 + threadIdx.x;
    const float4 a = ((const float4*)g_part[0])[i];
    const float4 b = ((const float4*)g_part[1])[i];
    float4 r;
    r.x = a.x + b.x; r.y = a.y + b.y; r.z = a.z + b.z; r.w = a.w + b.w;
    ((float4*)out)[i] = r;
}

extern "C" void kernel_launch(void* const* d_in, const int* in_sizes, int n_in,
                              void* d_out, int out_size) {
    const float* x     = (const float*)d_in[0];
    const float* phi   = (const float*)d_in[1];
    const float* sigma = (const float*)d_in[2];
    const float* Mp    = (const float*)d_in[3];
    const float* Mm    = (const float*)d_in[4];
    const float* Mu    = (const float*)d_in[5];
    (void)in_sizes; (void)n_in; (void)out_size;

    k_twiddle<<<NFFT / 256, 256>>>();
    k_fft_fwd<<<D_DIM + K_F, 256>>>(x, phi);
    k_conv_inv<<<K_F * D_DIM, 256>>>();
    k_arfill<<<dim3(L_SEQ / 32, KU * D_DIM / 32), dim3(32, 8)>>>(x);
    k_mbig<<<C_TOT / 8, 256>>>(Mp, Mm, Mu, sigma);
    k_gemm<<<dim3(D_DIM / 96, L_SEQ / 128, 2), 256>>>();
    k_reduce<<<(L_SEQ * D_DIM / 4) / 256, 256>>>((float*)d_out);
}